// round 10
// baseline (speedup 1.0000x reference)
#include <cuda_runtime.h>
#include <math_constants.h>
#include <cstdint>

#define NB 2
#define NPTS 8192
#define NQ (NB * NPTS)
#define SLICES 16
#define SLICE_CAND (NPTS / SLICES)     // 512
#define SLICE_PAIRS (SLICE_CAND / 2)   // 256
#define QPB 256                        // queries per k4 block
#define K4_THREADS 128
#define TCH 16                         // tau sample chunks (128 cands each; sample = 2048)
#define CHCAND 128
#define CHPAIRS (CHCAND / 2)           // 64
#define NMINS (TCH * 4)                // bucket mins per query
#define SAMPLE (TCH * CHCAND)          // 2048
#define REST (NPTS - SAMPLE)           // 6144 unsampled points per batch
#define INF CUDART_INF_F
#define SENTINEL 0x7fffffff
#define FULLM 0xffffffffu

// Candidate pair layout: pair j -> g_pairs[2j]=(x0,x1,y0,y1), g_pairs[2j+1]=(z0,z1,w0,w1)
__device__ float4 g_pairs[NB * (NPTS / 2) * 2];
__device__ float4 g_pts[NB * NPTS];                // (x,y,z,|p|^2) by original index
// Partials, transposed for coalescing: [slice][k(0..2)][query]
__device__ float  g_pScore[SLICES * 3 * NQ];
__device__ int    g_pIdx[SLICES * 3 * NQ];
// Tau pipeline: bucket mins [chunk*4+bucket][query], then tau per query
__device__ float  g_tc[NMINS * NQ];
__device__ float  g_tau[NQ];

__device__ __forceinline__ uint64_t dup2(float v) {
    uint64_t r; asm("mov.b64 %0,{%1,%1};" : "=l"(r) : "f"(v)); return r;
}
__device__ __forceinline__ uint64_t fma2(uint64_t a, uint64_t b, uint64_t c) {
    uint64_t d; asm("fma.rn.f32x2 %0,%1,%2,%3;" : "=l"(d) : "l"(a), "l"(b), "l"(c)); return d;
}
__device__ __forceinline__ void unpack2(uint64_t v, float& lo, float& hi) {
    asm("mov.b64 {%0,%1},%2;" : "=f"(lo), "=f"(hi) : "l"(v));
}

#define INS3(bs0, bs1, bs2, bi0, bi1, bi2, s, id)            \
    if ((s) < (bs2)) {                                       \
        if ((s) < (bs1)) {                                   \
            bs2 = bs1; bi2 = bi1;                            \
            if ((s) < (bs0)) { bs1 = bs0; bi1 = bi0;         \
                               bs0 = (s); bi0 = (id); }      \
            else             { bs1 = (s); bi1 = (id); }      \
        } else { bs2 = (s); bi2 = (id); }                    \
    }

// Lexicographic (score, idx) insert — used where tie-break order matters.
#define LINS3(bs0, bs1, bs2, bi0, bi1, bi2, s, id)                           \
    if ((s) < (bs2) || ((s) == (bs2) && (id) < (bi2))) {                     \
        if ((s) < (bs1) || ((s) == (bs1) && (id) < (bi1))) {                 \
            bs2 = bs1; bi2 = bi1;                                            \
            if ((s) < (bs0) || ((s) == (bs0) && (id) < (bi0))) {             \
                bs1 = bs0; bi1 = bi0; bs0 = (s); bi0 = (id);                 \
            } else { bs1 = (s); bi1 = (id); }                                \
        } else { bs2 = (s); bi2 = (id); }                                    \
    }

// Fused prep + tau bucket-min kernel (unchanged from R9).
#define K12_PREP_BLOCKS ((NB * REST) / 128)                    // = 96

__global__ void __launch_bounds__(128)
k12_prep_tau(const float* __restrict__ xyz1,
             const float* __restrict__ xyz2,
             const float* __restrict__ flow1) {
    const int tid = threadIdx.x;
    const int blk = blockIdx.x;

    if (blk >= 2048) {
        int e = (blk - 2048) * 128 + tid;          // 0 .. NB*REST-1
        int b = e / REST;
        int n = SAMPLE + (e - b * REST);           // SAMPLE .. NPTS-1
        const float* X = xyz1 + b * 3 * NPTS;
        const float* F = flow1 + b * 3 * NPTS;
        float px = X[n]            + F[n];
        float py = X[NPTS + n]     + F[NPTS + n];
        float pz = X[2 * NPTS + n] + F[2 * NPTS + n];
        float pw = fmaf(px, px, fmaf(py, py, pz * pz));
        g_pts[b * NPTS + n] = make_float4(px, py, pz, pw);
        float ox = __shfl_xor_sync(FULLM, px, 1);
        float oy = __shfl_xor_sync(FULLM, py, 1);
        float oz = __shfl_xor_sync(FULLM, pz, 1);
        float ow = __shfl_xor_sync(FULLM, pw, 1);
        if ((n & 1) == 0) {
            int j = b * (NPTS / 2) + (n >> 1);
            g_pairs[2 * j]     = make_float4(px, ox, py, oy);
            g_pairs[2 * j + 1] = make_float4(pz, oz, pw, ow);
        }
        return;
    }

    __shared__ float4 shp[CHPAIRS * 2];            // 2 KB chunk
    const int ch   = blk & (TCH - 1);
    const int qblk = blk >> 4;                     // 0..127; 64 qblks per batch
    const int b    = qblk >> 6;

    {
        const int c = ch * CHCAND + tid;
        const float* X = xyz1 + b * 3 * NPTS;
        const float* F = flow1 + b * 3 * NPTS;
        float px = X[c]            + F[c];
        float py = X[NPTS + c]     + F[NPTS + c];
        float pz = X[2 * NPTS + c] + F[2 * NPTS + c];
        float pw = fmaf(px, px, fmaf(py, py, pz * pz));
        float ox = __shfl_xor_sync(FULLM, px, 1);
        float oy = __shfl_xor_sync(FULLM, py, 1);
        float oz = __shfl_xor_sync(FULLM, pz, 1);
        float ow = __shfl_xor_sync(FULLM, pw, 1);
        if ((tid & 1) == 0) {
            int jj = tid >> 1;
            shp[2 * jj]     = make_float4(px, ox, py, oy);
            shp[2 * jj + 1] = make_float4(pz, oz, pw, ow);
        }
        if ((qblk & 63) == 0) {                    // writer block for (b, ch)
            g_pts[b * NPTS + c] = make_float4(px, py, pz, pw);
            if ((tid & 1) == 0) {
                int j = b * (NPTS / 2) + (c >> 1);
                g_pairs[2 * j]     = make_float4(px, ox, py, oy);
                g_pairs[2 * j + 1] = make_float4(pz, oz, pw, ow);
            }
        }
    }
    __syncthreads();

    const int q = qblk * 128 + tid;
    const int n = q & (NPTS - 1);
    const float* X2 = xyz2 + b * 3 * NPTS;
    const float qx = X2[n], qy = X2[NPTS + n], qz = X2[2 * NPTS + n];
    const uint64_t mx = dup2(-2.f * qx), my = dup2(-2.f * qy), mz = dup2(-2.f * qz);

    const ulonglong2* src = reinterpret_cast<const ulonglong2*>(shp);
    float m0 = INF, m1 = INF, m2 = INF, m3 = INF;
#pragma unroll 4
    for (int j = 0; j < CHPAIRS; j += 2) {
        ulonglong2 u0 = src[2 * j];
        ulonglong2 u1 = src[2 * j + 1];
        ulonglong2 v0 = src[2 * j + 2];
        ulonglong2 v1 = src[2 * j + 3];
        float a0, a1, c0, c1;
        unpack2(fma2(u0.x, mx, fma2(u0.y, my, fma2(u1.x, mz, u1.y))), a0, a1);
        unpack2(fma2(v0.x, mx, fma2(v0.y, my, fma2(v1.x, mz, v1.y))), c0, c1);
        m0 = fminf(m0, a0);
        m1 = fminf(m1, a1);
        m2 = fminf(m2, c0);
        m3 = fminf(m3, c1);
    }
    g_tc[(ch * 4 + 0) * NQ + q] = m0;
    g_tc[(ch * 4 + 1) * NQ + q] = m1;
    g_tc[(ch * 4 + 2) * NQ + q] = m2;
    g_tc[(ch * 4 + 3) * NQ + q] = m3;
}

// 3rd smallest of the 64 bucket mins (64 distinct candidates => >= global 3rd best).
__global__ void k3_tau2() {
    int q = blockIdx.x * blockDim.x + threadIdx.x;
    if (q >= NQ) return;
    float b0 = INF, b1 = INF, b2 = INF;
#pragma unroll 8
    for (int c = 0; c < NMINS; c++) {
        float s = g_tc[c * NQ + q];
        float t = fmaxf(b0, s);  b0 = fminf(b0, s);
        float u = fmaxf(b1, t);  b1 = fminf(b1, t);
        b2 = fminf(b2, u);
    }
    g_tau[q] = nextafterf(b2, CUDART_INF_F);
}

// 256 queries/block vs one 512-candidate slice (unchanged from R8/R9 — measured 33.4us).
__global__ void __launch_bounds__(K4_THREADS)
k4_scan(const float* __restrict__ xyz2) {
    __shared__ float4 sh[SLICE_PAIRS * 2];   // 8 KB

    const int blk   = blockIdx.x;
    const int slice = blk & (SLICES - 1);
    const int qg    = blk >> 4;              // 0..63
    const int batch = qg >> 5;               // 32 qgroups per batch
    const int qbase = (qg & 31) * QPB;
    const int lane  = threadIdx.x & 31;
    const int w     = threadIdx.x >> 5;

    const float4* src = g_pairs + (size_t)(batch * (NPTS / 2) + slice * SLICE_PAIRS) * 2;
#pragma unroll
    for (int i = threadIdx.x; i < SLICE_PAIRS * 2; i += K4_THREADS)
        sh[i] = src[i];
    __syncthreads();

    const int qA = qbase + w * 64 + lane;
    const int qB = qA + 32;
    const int gqA = batch * NPTS + qA;
    const int gqB = batch * NPTS + qB;
    const float* X2 = xyz2 + batch * 3 * NPTS;
    const float aX = X2[qA], aY = X2[NPTS + qA], aZ = X2[2 * NPTS + qA];
    const float bX = X2[qB], bY = X2[NPTS + qB], bZ = X2[2 * NPTS + qB];

    const uint64_t Amx = dup2(-2.f * aX), Amy = dup2(-2.f * aY), Amz = dup2(-2.f * aZ);
    const uint64_t Bmx = dup2(-2.f * bX), Bmy = dup2(-2.f * bY), Bmz = dup2(-2.f * bZ);

    const float tA = g_tau[gqA];
    const float tB = g_tau[gqB];
    float As0 = tA, As1 = tA, As2 = tA;  int Ai0 = SENTINEL, Ai1 = SENTINEL, Ai2 = SENTINEL;
    float Bs0 = tB, Bs1 = tB, Bs2 = tB;  int Bi0 = SENTINEL, Bi1 = SENTINEL, Bi2 = SENTINEL;

    const uint32_t shbase = (uint32_t)__cvta_generic_to_shared(sh);
    const int cbase = slice * SLICE_CAND;

#pragma unroll 4
    for (int j = 0; j < SLICE_PAIRS; j += 2) {
        uint64_t xp0, yp0, zp0, wp0, xp1, yp1, zp1, wp1;
        const uint32_t addr = shbase + j * 32;
        asm("ld.shared.v2.u64 {%0,%1},[%2];"    : "=l"(xp0), "=l"(yp0) : "r"(addr));
        asm("ld.shared.v2.u64 {%0,%1},[%2+16];" : "=l"(zp0), "=l"(wp0) : "r"(addr));
        asm("ld.shared.v2.u64 {%0,%1},[%2+32];" : "=l"(xp1), "=l"(yp1) : "r"(addr));
        asm("ld.shared.v2.u64 {%0,%1},[%2+48];" : "=l"(zp1), "=l"(wp1) : "r"(addr));

        float a0, a1, a2, a3, b0, b1, b2, b3;
        unpack2(fma2(xp0, Amx, fma2(yp0, Amy, fma2(zp0, Amz, wp0))), a0, a1);
        unpack2(fma2(xp1, Amx, fma2(yp1, Amy, fma2(zp1, Amz, wp1))), a2, a3);
        unpack2(fma2(xp0, Bmx, fma2(yp0, Bmy, fma2(zp0, Bmz, wp0))), b0, b1);
        unpack2(fma2(xp1, Bmx, fma2(yp1, Bmy, fma2(zp1, Bmz, wp1))), b2, b3);

        if (fminf(fminf(a0, a1), fminf(a2, a3)) < As2) {
            const int id = cbase + 2 * j;
            INS3(As0, As1, As2, Ai0, Ai1, Ai2, a0, id);
            INS3(As0, As1, As2, Ai0, Ai1, Ai2, a1, id + 1);
            INS3(As0, As1, As2, Ai0, Ai1, Ai2, a2, id + 2);
            INS3(As0, As1, As2, Ai0, Ai1, Ai2, a3, id + 3);
        }
        if (fminf(fminf(b0, b1), fminf(b2, b3)) < Bs2) {
            const int id = cbase + 2 * j;
            INS3(Bs0, Bs1, Bs2, Bi0, Bi1, Bi2, b0, id);
            INS3(Bs0, Bs1, Bs2, Bi0, Bi1, Bi2, b1, id + 1);
            INS3(Bs0, Bs1, Bs2, Bi0, Bi1, Bi2, b2, id + 2);
            INS3(Bs0, Bs1, Bs2, Bi0, Bi1, Bi2, b3, id + 3);
        }
    }

    const int sb = slice * 3 * NQ;
    g_pScore[sb + 0 * NQ + gqA] = As0;  g_pIdx[sb + 0 * NQ + gqA] = Ai0;
    g_pScore[sb + 1 * NQ + gqA] = As1;  g_pIdx[sb + 1 * NQ + gqA] = Ai1;
    g_pScore[sb + 2 * NQ + gqA] = As2;  g_pIdx[sb + 2 * NQ + gqA] = Ai2;
    g_pScore[sb + 0 * NQ + gqB] = Bs0;  g_pIdx[sb + 0 * NQ + gqB] = Bi0;
    g_pScore[sb + 1 * NQ + gqB] = Bs1;  g_pIdx[sb + 1 * NQ + gqB] = Bi1;
    g_pScore[sb + 2 * NQ + gqB] = Bs2;  g_pIdx[sb + 2 * NQ + gqB] = Bi2;
}

// Warp-per-query merge of 48 slice partials via lexicographic butterfly reduction,
// then distributed epilogue (lanes 0-2). 8 queries per 256-thread block.
__global__ void __launch_bounds__(256)
k5_final(const float* __restrict__ xyz2,
         const float* __restrict__ flow1,
         float* __restrict__ out) {
    const int lane = threadIdx.x & 31;
    const int q = blockIdx.x * 8 + (threadIdx.x >> 5);
    const int b = q >> 13, n = q & (NPTS - 1);

    // Each lane loads entries lane and 32+lane (lane<16); forms sorted pair.
    float sa = g_pScore[lane * NQ + q];
    int   ia = g_pIdx[lane * NQ + q];
    float sb_ = INF;
    int   ib = SENTINEL;
    if (lane < 16) {
        sb_ = g_pScore[(32 + lane) * NQ + q];
        ib  = g_pIdx[(32 + lane) * NQ + q];
    }
    float bs0, bs1, bs2 = INF;
    int   bi0, bi1, bi2 = SENTINEL;
    if (sb_ < sa || (sb_ == sa && ib < ia)) { bs0 = sb_; bi0 = ib; bs1 = sa;  bi1 = ia; }
    else                                    { bs0 = sa;  bi0 = ia; bs1 = sb_; bi1 = ib; }

    // Butterfly merge (snapshot before exchange; lex compare keeps low-index ties).
#pragma unroll
    for (int off = 16; off > 0; off >>= 1) {
        float o0 = bs0, o1 = bs1, o2 = bs2;
        int   j0 = bi0, j1 = bi1, j2 = bi2;
        float rs0 = __shfl_xor_sync(FULLM, o0, off);
        int   ri0 = __shfl_xor_sync(FULLM, j0, off);
        float rs1 = __shfl_xor_sync(FULLM, o1, off);
        int   ri1 = __shfl_xor_sync(FULLM, j1, off);
        float rs2 = __shfl_xor_sync(FULLM, o2, off);
        int   ri2 = __shfl_xor_sync(FULLM, j2, off);
        LINS3(bs0, bs1, bs2, bi0, bi1, bi2, rs0, ri0);
        LINS3(bs0, bs1, bs2, bi0, bi1, bi2, rs1, ri1);
        LINS3(bs0, bs1, bs2, bi0, bi1, bi2, rs2, ri2);
    }

    // Distributed epilogue: lane k (0..2) handles neighbor k.
    const float* X2 = xyz2 + b * 3 * NPTS;
    const float qx = X2[n], qy = X2[NPTS + n], qz = X2[2 * NPTS + n];

    float inv = 0.f, cfx = 0.f, cfy = 0.f, cfz = 0.f;
    if (lane < 3) {
        int o = (lane == 0) ? bi0 : (lane == 1) ? bi1 : bi2;
        float4 p = g_pts[b * NPTS + o];
        float dx = p.x - qx, dy = p.y - qy, dz = p.z - qz;
        float d = sqrtf(fmaf(dx, dx, fmaf(dy, dy, dz * dz)));
        d = fmaxf(d, 1e-10f);
        inv = 1.0f / d;
        const float* F = flow1 + b * 3 * NPTS;
        cfx = F[o];
        cfy = F[NPTS + o];
        cfz = F[2 * NPTS + o];
    }
    // Ordered reductions over lanes 0..2 (match reference summation order).
    float i0 = __shfl_sync(FULLM, inv, 0);
    float i1 = __shfl_sync(FULLM, inv, 1);
    float i2 = __shfl_sync(FULLM, inv, 2);
    float rs = 1.0f / (i0 + i1 + i2);
    float w = inv * rs;
    float wfx = w * cfx, wfy = w * cfy, wfz = w * cfz;
    float fx = __shfl_sync(FULLM, wfx, 0) + __shfl_sync(FULLM, wfx, 1) + __shfl_sync(FULLM, wfx, 2);
    float fy = __shfl_sync(FULLM, wfy, 0) + __shfl_sync(FULLM, wfy, 1) + __shfl_sync(FULLM, wfy, 2);
    float fz = __shfl_sync(FULLM, wfz, 0) + __shfl_sync(FULLM, wfz, 1) + __shfl_sync(FULLM, wfz, 2);

    if (lane == 0) {
        float* O = out + b * 3 * NPTS;
        O[n]            = qx - fx;
        O[NPTS + n]     = qy - fy;
        O[2 * NPTS + n] = qz - fz;
    }
}

extern "C" void kernel_launch(void* const* d_in, const int* in_sizes, int n_in,
                              void* d_out, int out_size) {
    const float* xyz1  = (const float*)d_in[0];
    const float* xyz2  = (const float*)d_in[1];
    const float* flow1 = (const float*)d_in[2];
    float* out = (float*)d_out;

    k12_prep_tau<<<2048 + K12_PREP_BLOCKS, 128>>>(xyz1, xyz2, flow1);  // 2144 blocks
    k3_tau2<<<(NQ + 255) / 256, 256>>>();
    k4_scan<<<(NQ / QPB) * SLICES, K4_THREADS>>>(xyz2);                // 1024 blocks
    k5_final<<<NQ / 8, 256>>>(xyz2, flow1, out);                       // 2048 blocks
}

// round 11
// speedup vs baseline: 1.0179x; 1.0179x over previous
#include <cuda_runtime.h>
#include <math_constants.h>
#include <cstdint>

#define NB 2
#define NPTS 8192
#define NQ (NB * NPTS)
#define SLICES 8
#define SLICE_CAND (NPTS / SLICES)     // 1024
#define SLICE_PAIRS (SLICE_CAND / 2)   // 512
#define QPB 256                        // queries per k4 block
#define K4_THREADS 128
#define NENT (SLICES * 3)              // 24 partial entries per query
#define TCH 16                         // tau sample chunks (128 cands each; sample = 2048)
#define CHCAND 128
#define CHPAIRS (CHCAND / 2)           // 64
#define NMINS (TCH * 4)                // bucket mins per query
#define SAMPLE (TCH * CHCAND)          // 2048
#define REST (NPTS - SAMPLE)           // 6144 unsampled points per batch
#define INF CUDART_INF_F
#define SENTINEL 0x7fffffff
#define FULLM 0xffffffffu

// Candidate pair layout: pair j -> g_pairs[2j]=(x0,x1,y0,y1), g_pairs[2j+1]=(z0,z1,w0,w1)
__device__ float4 g_pairs[NB * (NPTS / 2) * 2];
__device__ float4 g_pts[NB * NPTS];                // (x,y,z,|p|^2) by original index
// Partials, transposed for coalescing: [slice*3+k][query]
__device__ float  g_pScore[NENT * NQ];
__device__ int    g_pIdx[NENT * NQ];
// Tau pipeline: bucket mins [chunk*4+bucket][query], then tau per query
__device__ float  g_tc[NMINS * NQ];
__device__ float  g_tau[NQ];

__device__ __forceinline__ uint64_t dup2(float v) {
    uint64_t r; asm("mov.b64 %0,{%1,%1};" : "=l"(r) : "f"(v)); return r;
}
__device__ __forceinline__ uint64_t fma2(uint64_t a, uint64_t b, uint64_t c) {
    uint64_t d; asm("fma.rn.f32x2 %0,%1,%2,%3;" : "=l"(d) : "l"(a), "l"(b), "l"(c)); return d;
}
__device__ __forceinline__ void unpack2(uint64_t v, float& lo, float& hi) {
    asm("mov.b64 {%0,%1},%2;" : "=f"(lo), "=f"(hi) : "l"(v));
}

#define INS3(bs0, bs1, bs2, bi0, bi1, bi2, s, id)            \
    if ((s) < (bs2)) {                                       \
        if ((s) < (bs1)) {                                   \
            bs2 = bs1; bi2 = bi1;                            \
            if ((s) < (bs0)) { bs1 = bs0; bi1 = bi0;         \
                               bs0 = (s); bi0 = (id); }      \
            else             { bs1 = (s); bi1 = (id); }      \
        } else { bs2 = (s); bi2 = (id); }                    \
    }

// Fused prep + tau bucket-min kernel (unchanged from R9).
#define K12_PREP_BLOCKS ((NB * REST) / 128)                    // = 96

__global__ void __launch_bounds__(128)
k12_prep_tau(const float* __restrict__ xyz1,
             const float* __restrict__ xyz2,
             const float* __restrict__ flow1) {
    const int tid = threadIdx.x;
    const int blk = blockIdx.x;

    if (blk >= 2048) {
        int e = (blk - 2048) * 128 + tid;          // 0 .. NB*REST-1
        int b = e / REST;
        int n = SAMPLE + (e - b * REST);           // SAMPLE .. NPTS-1
        const float* X = xyz1 + b * 3 * NPTS;
        const float* F = flow1 + b * 3 * NPTS;
        float px = X[n]            + F[n];
        float py = X[NPTS + n]     + F[NPTS + n];
        float pz = X[2 * NPTS + n] + F[2 * NPTS + n];
        float pw = fmaf(px, px, fmaf(py, py, pz * pz));
        g_pts[b * NPTS + n] = make_float4(px, py, pz, pw);
        float ox = __shfl_xor_sync(FULLM, px, 1);
        float oy = __shfl_xor_sync(FULLM, py, 1);
        float oz = __shfl_xor_sync(FULLM, pz, 1);
        float ow = __shfl_xor_sync(FULLM, pw, 1);
        if ((n & 1) == 0) {
            int j = b * (NPTS / 2) + (n >> 1);
            g_pairs[2 * j]     = make_float4(px, ox, py, oy);
            g_pairs[2 * j + 1] = make_float4(pz, oz, pw, ow);
        }
        return;
    }

    __shared__ float4 shp[CHPAIRS * 2];            // 2 KB chunk
    const int ch   = blk & (TCH - 1);
    const int qblk = blk >> 4;                     // 0..127; 64 qblks per batch
    const int b    = qblk >> 6;

    {
        const int c = ch * CHCAND + tid;
        const float* X = xyz1 + b * 3 * NPTS;
        const float* F = flow1 + b * 3 * NPTS;
        float px = X[c]            + F[c];
        float py = X[NPTS + c]     + F[NPTS + c];
        float pz = X[2 * NPTS + c] + F[2 * NPTS + c];
        float pw = fmaf(px, px, fmaf(py, py, pz * pz));
        float ox = __shfl_xor_sync(FULLM, px, 1);
        float oy = __shfl_xor_sync(FULLM, py, 1);
        float oz = __shfl_xor_sync(FULLM, pz, 1);
        float ow = __shfl_xor_sync(FULLM, pw, 1);
        if ((tid & 1) == 0) {
            int jj = tid >> 1;
            shp[2 * jj]     = make_float4(px, ox, py, oy);
            shp[2 * jj + 1] = make_float4(pz, oz, pw, ow);
        }
        if ((qblk & 63) == 0) {                    // writer block for (b, ch)
            g_pts[b * NPTS + c] = make_float4(px, py, pz, pw);
            if ((tid & 1) == 0) {
                int j = b * (NPTS / 2) + (c >> 1);
                g_pairs[2 * j]     = make_float4(px, ox, py, oy);
                g_pairs[2 * j + 1] = make_float4(pz, oz, pw, ow);
            }
        }
    }
    __syncthreads();

    const int q = qblk * 128 + tid;
    const int n = q & (NPTS - 1);
    const float* X2 = xyz2 + b * 3 * NPTS;
    const float qx = X2[n], qy = X2[NPTS + n], qz = X2[2 * NPTS + n];
    const uint64_t mx = dup2(-2.f * qx), my = dup2(-2.f * qy), mz = dup2(-2.f * qz);

    const ulonglong2* src = reinterpret_cast<const ulonglong2*>(shp);
    float m0 = INF, m1 = INF, m2 = INF, m3 = INF;
#pragma unroll 4
    for (int j = 0; j < CHPAIRS; j += 2) {
        ulonglong2 u0 = src[2 * j];
        ulonglong2 u1 = src[2 * j + 1];
        ulonglong2 v0 = src[2 * j + 2];
        ulonglong2 v1 = src[2 * j + 3];
        float a0, a1, c0, c1;
        unpack2(fma2(u0.x, mx, fma2(u0.y, my, fma2(u1.x, mz, u1.y))), a0, a1);
        unpack2(fma2(v0.x, mx, fma2(v0.y, my, fma2(v1.x, mz, v1.y))), c0, c1);
        m0 = fminf(m0, a0);
        m1 = fminf(m1, a1);
        m2 = fminf(m2, c0);
        m3 = fminf(m3, c1);
    }
    g_tc[(ch * 4 + 0) * NQ + q] = m0;
    g_tc[(ch * 4 + 1) * NQ + q] = m1;
    g_tc[(ch * 4 + 2) * NQ + q] = m2;
    g_tc[(ch * 4 + 3) * NQ + q] = m3;
}

// 3rd smallest of the 64 bucket mins (64 distinct candidates => >= global 3rd best).
__global__ void k3_tau2() {
    int q = blockIdx.x * blockDim.x + threadIdx.x;
    if (q >= NQ) return;
    float b0 = INF, b1 = INF, b2 = INF;
#pragma unroll 8
    for (int c = 0; c < NMINS; c++) {
        float s = g_tc[c * NQ + q];
        float t = fmaxf(b0, s);  b0 = fminf(b0, s);
        float u = fmaxf(b1, t);  b1 = fminf(b1, t);
        b2 = fminf(b2, u);
    }
    g_tau[q] = nextafterf(b2, CUDART_INF_F);
}

// 256 queries/block vs one 1024-candidate slice; tau-seeded trackers (SLICES=8).
__global__ void __launch_bounds__(K4_THREADS)
k4_scan(const float* __restrict__ xyz2) {
    __shared__ float4 sh[SLICE_PAIRS * 2];   // 16 KB

    const int blk   = blockIdx.x;
    const int slice = blk & (SLICES - 1);
    const int qg    = blk >> 3;              // 0..63
    const int batch = qg >> 5;               // 32 qgroups per batch
    const int qbase = (qg & 31) * QPB;
    const int lane  = threadIdx.x & 31;
    const int w     = threadIdx.x >> 5;

    const float4* src = g_pairs + (size_t)(batch * (NPTS / 2) + slice * SLICE_PAIRS) * 2;
#pragma unroll
    for (int i = threadIdx.x; i < SLICE_PAIRS * 2; i += K4_THREADS)
        sh[i] = src[i];
    __syncthreads();

    const int qA = qbase + w * 64 + lane;
    const int qB = qA + 32;
    const int gqA = batch * NPTS + qA;
    const int gqB = batch * NPTS + qB;
    const float* X2 = xyz2 + batch * 3 * NPTS;
    const float aX = X2[qA], aY = X2[NPTS + qA], aZ = X2[2 * NPTS + qA];
    const float bX = X2[qB], bY = X2[NPTS + qB], bZ = X2[2 * NPTS + qB];

    const uint64_t Amx = dup2(-2.f * aX), Amy = dup2(-2.f * aY), Amz = dup2(-2.f * aZ);
    const uint64_t Bmx = dup2(-2.f * bX), Bmy = dup2(-2.f * bY), Bmz = dup2(-2.f * bZ);

    const float tA = g_tau[gqA];
    const float tB = g_tau[gqB];
    float As0 = tA, As1 = tA, As2 = tA;  int Ai0 = SENTINEL, Ai1 = SENTINEL, Ai2 = SENTINEL;
    float Bs0 = tB, Bs1 = tB, Bs2 = tB;  int Bi0 = SENTINEL, Bi1 = SENTINEL, Bi2 = SENTINEL;

    const uint32_t shbase = (uint32_t)__cvta_generic_to_shared(sh);
    const int cbase = slice * SLICE_CAND;

#pragma unroll 4
    for (int j = 0; j < SLICE_PAIRS; j += 2) {
        uint64_t xp0, yp0, zp0, wp0, xp1, yp1, zp1, wp1;
        const uint32_t addr = shbase + j * 32;
        asm("ld.shared.v2.u64 {%0,%1},[%2];"    : "=l"(xp0), "=l"(yp0) : "r"(addr));
        asm("ld.shared.v2.u64 {%0,%1},[%2+16];" : "=l"(zp0), "=l"(wp0) : "r"(addr));
        asm("ld.shared.v2.u64 {%0,%1},[%2+32];" : "=l"(xp1), "=l"(yp1) : "r"(addr));
        asm("ld.shared.v2.u64 {%0,%1},[%2+48];" : "=l"(zp1), "=l"(wp1) : "r"(addr));

        float a0, a1, a2, a3, b0, b1, b2, b3;
        unpack2(fma2(xp0, Amx, fma2(yp0, Amy, fma2(zp0, Amz, wp0))), a0, a1);
        unpack2(fma2(xp1, Amx, fma2(yp1, Amy, fma2(zp1, Amz, wp1))), a2, a3);
        unpack2(fma2(xp0, Bmx, fma2(yp0, Bmy, fma2(zp0, Bmz, wp0))), b0, b1);
        unpack2(fma2(xp1, Bmx, fma2(yp1, Bmy, fma2(zp1, Bmz, wp1))), b2, b3);

        if (fminf(fminf(a0, a1), fminf(a2, a3)) < As2) {
            const int id = cbase + 2 * j;
            INS3(As0, As1, As2, Ai0, Ai1, Ai2, a0, id);
            INS3(As0, As1, As2, Ai0, Ai1, Ai2, a1, id + 1);
            INS3(As0, As1, As2, Ai0, Ai1, Ai2, a2, id + 2);
            INS3(As0, As1, As2, Ai0, Ai1, Ai2, a3, id + 3);
        }
        if (fminf(fminf(b0, b1), fminf(b2, b3)) < Bs2) {
            const int id = cbase + 2 * j;
            INS3(Bs0, Bs1, Bs2, Bi0, Bi1, Bi2, b0, id);
            INS3(Bs0, Bs1, Bs2, Bi0, Bi1, Bi2, b1, id + 1);
            INS3(Bs0, Bs1, Bs2, Bi0, Bi1, Bi2, b2, id + 2);
            INS3(Bs0, Bs1, Bs2, Bi0, Bi1, Bi2, b3, id + 3);
        }
    }

    const int sb = slice * 3 * NQ;
    g_pScore[sb + 0 * NQ + gqA] = As0;  g_pIdx[sb + 0 * NQ + gqA] = Ai0;
    g_pScore[sb + 1 * NQ + gqA] = As1;  g_pIdx[sb + 1 * NQ + gqA] = Ai1;
    g_pScore[sb + 2 * NQ + gqA] = As2;  g_pIdx[sb + 2 * NQ + gqA] = Ai2;
    g_pScore[sb + 0 * NQ + gqB] = Bs0;  g_pIdx[sb + 0 * NQ + gqB] = Bi0;
    g_pScore[sb + 1 * NQ + gqB] = Bs1;  g_pIdx[sb + 1 * NQ + gqB] = Bi1;
    g_pScore[sb + 2 * NQ + gqB] = Bs2;  g_pIdx[sb + 2 * NQ + gqB] = Bi2;
}

// Thread-per-query merge: front-batched coalesced register loads of all 24
// entries (high MLP), then strict-< slice-ascending merge, then epilogue.
__global__ void __launch_bounds__(128)
k5_final(const float* __restrict__ xyz2,
         const float* __restrict__ flow1,
         float* __restrict__ out) {
    const int q = blockIdx.x * 128 + threadIdx.x;
    const int b = q >> 13, n = q & (NPTS - 1);

    float s[NENT];
    int   id[NENT];
#pragma unroll
    for (int e = 0; e < NENT; e++) s[e] = g_pScore[e * NQ + q];
#pragma unroll
    for (int e = 0; e < NENT; e++) id[e] = g_pIdx[e * NQ + q];

    float bs0 = INF, bs1 = INF, bs2 = INF;
    int   bi0 = 0,   bi1 = 0,   bi2 = 0;
#pragma unroll
    for (int e = 0; e < NENT; e++) {
        INS3(bs0, bs1, bs2, bi0, bi1, bi2, s[e], id[e]);
    }

    const float* X2 = xyz2 + b * 3 * NPTS;
    const float qx = X2[n], qy = X2[NPTS + n], qz = X2[2 * NPTS + n];

    const float4* pts = g_pts + b * NPTS;
    int   pp[3] = { bi0, bi1, bi2 };
    float wk[3];
    float wsum = 0.f;
#pragma unroll
    for (int k = 0; k < 3; k++) {
        float4 p = pts[pp[k]];
        float dx = p.x - qx, dy = p.y - qy, dz = p.z - qz;
        float d = sqrtf(fmaf(dx, dx, fmaf(dy, dy, dz * dz)));
        d = fmaxf(d, 1e-10f);
        float inv = 1.0f / d;
        wk[k] = inv;
        wsum += inv;
    }
    const float rs = 1.0f / wsum;

    const float* F = flow1 + b * 3 * NPTS;
    float fx = 0.f, fy = 0.f, fz = 0.f;
#pragma unroll
    for (int k = 0; k < 3; k++) {
        int o = pp[k];
        float ww = wk[k] * rs;
        fx = fmaf(ww, F[o],            fx);
        fy = fmaf(ww, F[NPTS + o],     fy);
        fz = fmaf(ww, F[2 * NPTS + o], fz);
    }

    float* O = out + b * 3 * NPTS;
    O[n]            = qx - fx;
    O[NPTS + n]     = qy - fy;
    O[2 * NPTS + n] = qz - fz;
}

extern "C" void kernel_launch(void* const* d_in, const int* in_sizes, int n_in,
                              void* d_out, int out_size) {
    const float* xyz1  = (const float*)d_in[0];
    const float* xyz2  = (const float*)d_in[1];
    const float* flow1 = (const float*)d_in[2];
    float* out = (float*)d_out;

    k12_prep_tau<<<2048 + K12_PREP_BLOCKS, 128>>>(xyz1, xyz2, flow1);  // 2144 blocks
    k3_tau2<<<(NQ + 255) / 256, 256>>>();
    k4_scan<<<(NQ / QPB) * SLICES, K4_THREADS>>>(xyz2);                // 512 blocks
    k5_final<<<NQ / 128, 128>>>(xyz2, flow1, out);                     // 128 blocks
}

// round 12
// speedup vs baseline: 1.1721x; 1.1515x over previous
#include <cuda_runtime.h>
#include <math_constants.h>
#include <cstdint>

#define NB 2
#define NPTS 8192
#define NQ (NB * NPTS)
#define SLICES 16
#define SLICE_CAND (NPTS / SLICES)     // 512
#define SLICE_PAIRS (SLICE_CAND / 2)   // 256
#define QPB 256                        // queries per k4 block
#define K4_THREADS 128
#define NENT (SLICES * 3)              // 48 partial entries per query
#define TCH 16                         // tau sample chunks (128 cands each; sample = 2048)
#define CHCAND 128
#define CHPAIRS (CHCAND / 2)           // 64
#define NMINS (TCH * 4)                // bucket mins per query
#define SAMPLE (TCH * CHCAND)          // 2048
#define REST (NPTS - SAMPLE)           // 6144 unsampled points per batch
#define INF CUDART_INF_F
#define SENTINEL 0x7fffffff
#define FULLM 0xffffffffu

// Candidate pair layout: pair j -> g_pairs[2j]=(x0,x1,y0,y1), g_pairs[2j+1]=(z0,z1,w0,w1)
__device__ float4 g_pairs[NB * (NPTS / 2) * 2];
__device__ float4 g_pts[NB * NPTS];                // (x,y,z,|p|^2) by original index
// Partials, transposed for coalescing: [slice*3+k][query]
__device__ float  g_pScore[NENT * NQ];
__device__ int    g_pIdx[NENT * NQ];
// Tau pipeline: bucket mins [chunk*4+bucket][query], then tau per query
__device__ float  g_tc[NMINS * NQ];
__device__ float  g_tau[NQ];

__device__ __forceinline__ uint64_t dup2(float v) {
    uint64_t r; asm("mov.b64 %0,{%1,%1};" : "=l"(r) : "f"(v)); return r;
}
__device__ __forceinline__ uint64_t fma2(uint64_t a, uint64_t b, uint64_t c) {
    uint64_t d; asm("fma.rn.f32x2 %0,%1,%2,%3;" : "=l"(d) : "l"(a), "l"(b), "l"(c)); return d;
}
__device__ __forceinline__ void unpack2(uint64_t v, float& lo, float& hi) {
    asm("mov.b64 {%0,%1},%2;" : "=f"(lo), "=f"(hi) : "l"(v));
}

// Branchy insert (fast when guarded by a rare outer test) — used in k4.
#define INS3(bs0, bs1, bs2, bi0, bi1, bi2, s, id)            \
    if ((s) < (bs2)) {                                       \
        if ((s) < (bs1)) {                                   \
            bs2 = bs1; bi2 = bi1;                            \
            if ((s) < (bs0)) { bs1 = bs0; bi1 = bi0;         \
                               bs0 = (s); bi0 = (id); }      \
            else             { bs1 = (s); bi1 = (id); }      \
        } else { bs2 = (s); bi2 = (id); }                    \
    }

// Branchless (select-based) insert — used in k5 so loads can be pipelined.
#define FINS3(s0, s1, s2, i0, i1, i2, s, id) do {            \
    bool p2 = (s) < (s2);                                    \
    bool p1 = (s) < (s1);                                    \
    bool p0 = (s) < (s0);                                    \
    s2 = p1 ? (s1) : (p2 ? (s) : (s2));                      \
    i2 = p1 ? (i1) : (p2 ? (id) : (i2));                     \
    s1 = p0 ? (s0) : (p1 ? (s) : (s1));                      \
    i1 = p0 ? (i0) : (p1 ? (id) : (i1));                     \
    s0 = p0 ? (s) : (s0);                                    \
    i0 = p0 ? (id) : (i0);                                   \
} while (0)

// Fused prep + tau bucket-min kernel (unchanged from R9).
#define K12_PREP_BLOCKS ((NB * REST) / 128)                    // = 96

__global__ void __launch_bounds__(128)
k12_prep_tau(const float* __restrict__ xyz1,
             const float* __restrict__ xyz2,
             const float* __restrict__ flow1) {
    const int tid = threadIdx.x;
    const int blk = blockIdx.x;

    if (blk >= 2048) {
        int e = (blk - 2048) * 128 + tid;          // 0 .. NB*REST-1
        int b = e / REST;
        int n = SAMPLE + (e - b * REST);           // SAMPLE .. NPTS-1
        const float* X = xyz1 + b * 3 * NPTS;
        const float* F = flow1 + b * 3 * NPTS;
        float px = X[n]            + F[n];
        float py = X[NPTS + n]     + F[NPTS + n];
        float pz = X[2 * NPTS + n] + F[2 * NPTS + n];
        float pw = fmaf(px, px, fmaf(py, py, pz * pz));
        g_pts[b * NPTS + n] = make_float4(px, py, pz, pw);
        float ox = __shfl_xor_sync(FULLM, px, 1);
        float oy = __shfl_xor_sync(FULLM, py, 1);
        float oz = __shfl_xor_sync(FULLM, pz, 1);
        float ow = __shfl_xor_sync(FULLM, pw, 1);
        if ((n & 1) == 0) {
            int j = b * (NPTS / 2) + (n >> 1);
            g_pairs[2 * j]     = make_float4(px, ox, py, oy);
            g_pairs[2 * j + 1] = make_float4(pz, oz, pw, ow);
        }
        return;
    }

    __shared__ float4 shp[CHPAIRS * 2];            // 2 KB chunk
    const int ch   = blk & (TCH - 1);
    const int qblk = blk >> 4;                     // 0..127; 64 qblks per batch
    const int b    = qblk >> 6;

    {
        const int c = ch * CHCAND + tid;
        const float* X = xyz1 + b * 3 * NPTS;
        const float* F = flow1 + b * 3 * NPTS;
        float px = X[c]            + F[c];
        float py = X[NPTS + c]     + F[NPTS + c];
        float pz = X[2 * NPTS + c] + F[2 * NPTS + c];
        float pw = fmaf(px, px, fmaf(py, py, pz * pz));
        float ox = __shfl_xor_sync(FULLM, px, 1);
        float oy = __shfl_xor_sync(FULLM, py, 1);
        float oz = __shfl_xor_sync(FULLM, pz, 1);
        float ow = __shfl_xor_sync(FULLM, pw, 1);
        if ((tid & 1) == 0) {
            int jj = tid >> 1;
            shp[2 * jj]     = make_float4(px, ox, py, oy);
            shp[2 * jj + 1] = make_float4(pz, oz, pw, ow);
        }
        if ((qblk & 63) == 0) {                    // writer block for (b, ch)
            g_pts[b * NPTS + c] = make_float4(px, py, pz, pw);
            if ((tid & 1) == 0) {
                int j = b * (NPTS / 2) + (c >> 1);
                g_pairs[2 * j]     = make_float4(px, ox, py, oy);
                g_pairs[2 * j + 1] = make_float4(pz, oz, pw, ow);
            }
        }
    }
    __syncthreads();

    const int q = qblk * 128 + tid;
    const int n = q & (NPTS - 1);
    const float* X2 = xyz2 + b * 3 * NPTS;
    const float qx = X2[n], qy = X2[NPTS + n], qz = X2[2 * NPTS + n];
    const uint64_t mx = dup2(-2.f * qx), my = dup2(-2.f * qy), mz = dup2(-2.f * qz);

    const ulonglong2* src = reinterpret_cast<const ulonglong2*>(shp);
    float m0 = INF, m1 = INF, m2 = INF, m3 = INF;
#pragma unroll 4
    for (int j = 0; j < CHPAIRS; j += 2) {
        ulonglong2 u0 = src[2 * j];
        ulonglong2 u1 = src[2 * j + 1];
        ulonglong2 v0 = src[2 * j + 2];
        ulonglong2 v1 = src[2 * j + 3];
        float a0, a1, c0, c1;
        unpack2(fma2(u0.x, mx, fma2(u0.y, my, fma2(u1.x, mz, u1.y))), a0, a1);
        unpack2(fma2(v0.x, mx, fma2(v0.y, my, fma2(v1.x, mz, v1.y))), c0, c1);
        m0 = fminf(m0, a0);
        m1 = fminf(m1, a1);
        m2 = fminf(m2, c0);
        m3 = fminf(m3, c1);
    }
    g_tc[(ch * 4 + 0) * NQ + q] = m0;
    g_tc[(ch * 4 + 1) * NQ + q] = m1;
    g_tc[(ch * 4 + 2) * NQ + q] = m2;
    g_tc[(ch * 4 + 3) * NQ + q] = m3;
}

// 3rd smallest of the 64 bucket mins (64 distinct candidates => >= global 3rd best).
__global__ void k3_tau2() {
    int q = blockIdx.x * blockDim.x + threadIdx.x;
    if (q >= NQ) return;
    float b0 = INF, b1 = INF, b2 = INF;
#pragma unroll 8
    for (int c = 0; c < NMINS; c++) {
        float s = g_tc[c * NQ + q];
        float t = fmaxf(b0, s);  b0 = fminf(b0, s);
        float u = fmaxf(b1, t);  b1 = fminf(b1, t);
        b2 = fminf(b2, u);
    }
    g_tau[q] = nextafterf(b2, CUDART_INF_F);
}

// 256 queries/block vs one 512-candidate slice (R8/R9 config — measured 33.4us).
__global__ void __launch_bounds__(K4_THREADS)
k4_scan(const float* __restrict__ xyz2) {
    __shared__ float4 sh[SLICE_PAIRS * 2];   // 8 KB

    const int blk   = blockIdx.x;
    const int slice = blk & (SLICES - 1);
    const int qg    = blk >> 4;              // 0..63
    const int batch = qg >> 5;               // 32 qgroups per batch
    const int qbase = (qg & 31) * QPB;
    const int lane  = threadIdx.x & 31;
    const int w     = threadIdx.x >> 5;

    const float4* src = g_pairs + (size_t)(batch * (NPTS / 2) + slice * SLICE_PAIRS) * 2;
#pragma unroll
    for (int i = threadIdx.x; i < SLICE_PAIRS * 2; i += K4_THREADS)
        sh[i] = src[i];
    __syncthreads();

    const int qA = qbase + w * 64 + lane;
    const int qB = qA + 32;
    const int gqA = batch * NPTS + qA;
    const int gqB = batch * NPTS + qB;
    const float* X2 = xyz2 + batch * 3 * NPTS;
    const float aX = X2[qA], aY = X2[NPTS + qA], aZ = X2[2 * NPTS + qA];
    const float bX = X2[qB], bY = X2[NPTS + qB], bZ = X2[2 * NPTS + qB];

    const uint64_t Amx = dup2(-2.f * aX), Amy = dup2(-2.f * aY), Amz = dup2(-2.f * aZ);
    const uint64_t Bmx = dup2(-2.f * bX), Bmy = dup2(-2.f * bY), Bmz = dup2(-2.f * bZ);

    const float tA = g_tau[gqA];
    const float tB = g_tau[gqB];
    float As0 = tA, As1 = tA, As2 = tA;  int Ai0 = SENTINEL, Ai1 = SENTINEL, Ai2 = SENTINEL;
    float Bs0 = tB, Bs1 = tB, Bs2 = tB;  int Bi0 = SENTINEL, Bi1 = SENTINEL, Bi2 = SENTINEL;

    const uint32_t shbase = (uint32_t)__cvta_generic_to_shared(sh);
    const int cbase = slice * SLICE_CAND;

#pragma unroll 4
    for (int j = 0; j < SLICE_PAIRS; j += 2) {
        uint64_t xp0, yp0, zp0, wp0, xp1, yp1, zp1, wp1;
        const uint32_t addr = shbase + j * 32;
        asm("ld.shared.v2.u64 {%0,%1},[%2];"    : "=l"(xp0), "=l"(yp0) : "r"(addr));
        asm("ld.shared.v2.u64 {%0,%1},[%2+16];" : "=l"(zp0), "=l"(wp0) : "r"(addr));
        asm("ld.shared.v2.u64 {%0,%1},[%2+32];" : "=l"(xp1), "=l"(yp1) : "r"(addr));
        asm("ld.shared.v2.u64 {%0,%1},[%2+48];" : "=l"(zp1), "=l"(wp1) : "r"(addr));

        float a0, a1, a2, a3, b0, b1, b2, b3;
        unpack2(fma2(xp0, Amx, fma2(yp0, Amy, fma2(zp0, Amz, wp0))), a0, a1);
        unpack2(fma2(xp1, Amx, fma2(yp1, Amy, fma2(zp1, Amz, wp1))), a2, a3);
        unpack2(fma2(xp0, Bmx, fma2(yp0, Bmy, fma2(zp0, Bmz, wp0))), b0, b1);
        unpack2(fma2(xp1, Bmx, fma2(yp1, Bmy, fma2(zp1, Bmz, wp1))), b2, b3);

        if (fminf(fminf(a0, a1), fminf(a2, a3)) < As2) {
            const int id = cbase + 2 * j;
            INS3(As0, As1, As2, Ai0, Ai1, Ai2, a0, id);
            INS3(As0, As1, As2, Ai0, Ai1, Ai2, a1, id + 1);
            INS3(As0, As1, As2, Ai0, Ai1, Ai2, a2, id + 2);
            INS3(As0, As1, As2, Ai0, Ai1, Ai2, a3, id + 3);
        }
        if (fminf(fminf(b0, b1), fminf(b2, b3)) < Bs2) {
            const int id = cbase + 2 * j;
            INS3(Bs0, Bs1, Bs2, Bi0, Bi1, Bi2, b0, id);
            INS3(Bs0, Bs1, Bs2, Bi0, Bi1, Bi2, b1, id + 1);
            INS3(Bs0, Bs1, Bs2, Bi0, Bi1, Bi2, b2, id + 2);
            INS3(Bs0, Bs1, Bs2, Bi0, Bi1, Bi2, b3, id + 3);
        }
    }

    const int sb = slice * 3 * NQ;
    g_pScore[sb + 0 * NQ + gqA] = As0;  g_pIdx[sb + 0 * NQ + gqA] = Ai0;
    g_pScore[sb + 1 * NQ + gqA] = As1;  g_pIdx[sb + 1 * NQ + gqA] = Ai1;
    g_pScore[sb + 2 * NQ + gqA] = As2;  g_pIdx[sb + 2 * NQ + gqA] = Ai2;
    g_pScore[sb + 0 * NQ + gqB] = Bs0;  g_pIdx[sb + 0 * NQ + gqB] = Bi0;
    g_pScore[sb + 1 * NQ + gqB] = Bs1;  g_pIdx[sb + 1 * NQ + gqB] = Bi1;
    g_pScore[sb + 2 * NQ + gqB] = Bs2;  g_pIdx[sb + 2 * NQ + gqB] = Bi2;
}

// Thread-per-query merge: fully-unrolled BRANCHLESS streaming merge of 48 entries
// (no control flow -> deep load pipelining), then epilogue.
__global__ void __launch_bounds__(256)
k5_final(const float* __restrict__ xyz2,
         const float* __restrict__ flow1,
         float* __restrict__ out) {
    const int q = blockIdx.x * 256 + threadIdx.x;
    const int b = q >> 13, n = q & (NPTS - 1);

    float bs0 = INF, bs1 = INF, bs2 = INF;
    int   bi0 = 0,   bi1 = 0,   bi2 = 0;
#pragma unroll
    for (int e = 0; e < NENT; e++) {
        float s  = g_pScore[e * NQ + q];
        int   iv = g_pIdx[e * NQ + q];
        FINS3(bs0, bs1, bs2, bi0, bi1, bi2, s, iv);
    }

    const float* X2 = xyz2 + b * 3 * NPTS;
    const float qx = X2[n], qy = X2[NPTS + n], qz = X2[2 * NPTS + n];

    const float4* pts = g_pts + b * NPTS;
    int   pp[3] = { bi0, bi1, bi2 };
    float wk[3];
    float wsum = 0.f;
#pragma unroll
    for (int k = 0; k < 3; k++) {
        float4 p = pts[pp[k]];
        float dx = p.x - qx, dy = p.y - qy, dz = p.z - qz;
        float d = sqrtf(fmaf(dx, dx, fmaf(dy, dy, dz * dz)));
        d = fmaxf(d, 1e-10f);
        float inv = 1.0f / d;
        wk[k] = inv;
        wsum += inv;
    }
    const float rs = 1.0f / wsum;

    const float* F = flow1 + b * 3 * NPTS;
    float fx = 0.f, fy = 0.f, fz = 0.f;
#pragma unroll
    for (int k = 0; k < 3; k++) {
        int o = pp[k];
        float ww = wk[k] * rs;
        fx = fmaf(ww, F[o],            fx);
        fy = fmaf(ww, F[NPTS + o],     fy);
        fz = fmaf(ww, F[2 * NPTS + o], fz);
    }

    float* O = out + b * 3 * NPTS;
    O[n]            = qx - fx;
    O[NPTS + n]     = qy - fy;
    O[2 * NPTS + n] = qz - fz;
}

extern "C" void kernel_launch(void* const* d_in, const int* in_sizes, int n_in,
                              void* d_out, int out_size) {
    const float* xyz1  = (const float*)d_in[0];
    const float* xyz2  = (const float*)d_in[1];
    const float* flow1 = (const float*)d_in[2];
    float* out = (float*)d_out;

    k12_prep_tau<<<2048 + K12_PREP_BLOCKS, 128>>>(xyz1, xyz2, flow1);  // 2144 blocks
    k3_tau2<<<(NQ + 255) / 256, 256>>>();
    k4_scan<<<(NQ / QPB) * SLICES, K4_THREADS>>>(xyz2);                // 1024 blocks
    k5_final<<<NQ / 256, 256>>>(xyz2, flow1, out);                     // 64 blocks
}